// round 15
// baseline (speedup 1.0000x reference)
#include <cuda_runtime.h>
#include <cstdint>

#define BATCH   16
#define NANCH   102000
#define NCLS    35
#define STRIDE  40          // 4 box + 1 obj + 35 cls
#define PRE     1024
#define PRE2    2048        // keys array stride per batch (slack for boundary bin)
#define MAXD    300
#define CONF_T  0.25f
#define IOU_T   0.45f
#define BINS    4096
#define SEGCAP  128         // max keys per bin segment the warp sort handles

// ---------------- device scratch (all self-cleaning across graph replays) -------
__device__ __align__(16) float    g_scores[BATCH * NANCH];
__device__ __align__(16) unsigned g_hist[BATCH * BINS];     // zeroed by thresh, reused as
                                                            // placement counters, zeroed by sortg
__device__ __align__(16) unsigned g_segbase[BATCH * BINS];  // suffix sums (rewritten each run)
__device__ __align__(16) int      g_B1[BATCH];
__device__ __align__(16) unsigned long long g_keys[BATCH * PRE2];
__device__ __align__(16) int      g_selidx[BATCH * PRE];
__device__ __align__(16) float    g_selscore[BATCH * PRE];
__device__ __align__(16) float    g_boxes[BATCH * PRE * 4];
__device__ __align__(16) float    g_cls[BATCH * PRE];
__device__ __align__(16) unsigned g_mask[BATCH * PRE * 32];

// ---------------- kernel 1: score + histogram (smem-staged, coalesced) ----------
__global__ void __launch_bounds__(256) score_kernel(const float* __restrict__ pred) {
    __shared__ float st[256 * 41];              // 41-float stride: conflict-free reads
    int b = blockIdx.y;
    int a0 = blockIdx.x * 256;
    int nrem = NANCH - a0; if (nrem > 256) nrem = 256;
    const float4* gp = (const float4*)(pred + ((size_t)b * NANCH + a0) * STRIDE);
    int nv4 = nrem * 10;                        // 10 float4 per anchor
    for (int g = threadIdx.x; g < nv4; g += 256) {
        float4 v = gp[g];
        int anchor = g / 10;
        int ew = (g - anchor * 10) * 4;
        float* d = st + anchor * 41 + ew;
        d[0] = v.x; d[1] = v.y; d[2] = v.z; d[3] = v.w;
    }
    __syncthreads();
    int t = threadIdx.x;
    if (t < nrem) {
        const float* s = st + t * 41;
        float obj = s[4];
        float conf = 0.0f;
#pragma unroll
        for (int c = 0; c < NCLS; c++)
            conf = fmaxf(conf, __fmul_rn(s[5 + c], obj));
        float sc = (obj > CONF_T && conf > CONF_T) ? conf : 0.0f;
        g_scores[(size_t)b * NANCH + a0 + t] = sc;
        if (sc > 0.0f) {
            int bin = (int)(sc * 4096.0f); bin = bin > 4095 ? 4095 : bin;
            atomicAdd(&g_hist[b * BINS + bin], 1u);
        }
    }
}

// ------- kernel 2: threshold bin + per-bin segment bases (self-cleans hist) ------
__global__ void __launch_bounds__(1024) thresh_kernel() {
    int b = blockIdx.x, t = threadIdx.x;
    int lane = t & 31, w = t >> 5;
    __shared__ unsigned warpsum[32];
    __shared__ int sB1;
    uint4 h = ((const uint4*)(g_hist + b * BINS))[t];
    ((uint4*)(g_hist + b * BINS))[t] = make_uint4(0u, 0u, 0u, 0u);  // zero -> counters
    unsigned s = h.x + h.y + h.z + h.w;
    unsigned sacc = s;
#pragma unroll
    for (int o = 1; o < 32; o <<= 1) {
        unsigned v = __shfl_down_sync(0xffffffffu, sacc, o);
        if (lane + o < 32) sacc += v;
    }
    if (lane == 0) warpsum[w] = sacc;
    __syncthreads();
    if (t < 32) {
        unsigned ws = warpsum[t];
        unsigned wacc = ws;
#pragma unroll
        for (int o = 1; o < 32; o <<= 1) {
            unsigned v = __shfl_down_sync(0xffffffffu, wacc, o);
            if (t + o < 32) wacc += v;
        }
        warpsum[t] = wacc - ws;     // exclusive suffix over warps
    }
    __syncthreads();
    unsigned S_incl = sacc + warpsum[w];     // count(bins >= 4t)
    if (t == 0) sB1 = 0;                     // fallback: total < PRE -> take everything
    __syncthreads();
    unsigned S4 = S_incl - s;                // count(bins >= 4t+4) == base[4t+3]
    unsigned S3 = S4 + h.w;                  // base[4t+2]
    unsigned S2 = S3 + h.z;                  // base[4t+1]
    unsigned S1 = S2 + h.y;                  // base[4t+0]
    unsigned S0 = S1 + h.x;
    // per-bin suffix bases: segbase[bin] = count(bins' > bin)
    ((uint4*)(g_segbase + b * BINS))[t] = make_uint4(S1, S2, S3, S4);
    if (S3 >= PRE && S4 < PRE) sB1 = 4 * t + 3;
    if (S2 >= PRE && S3 < PRE) sB1 = 4 * t + 2;
    if (S1 >= PRE && S2 < PRE) sB1 = 4 * t + 1;
    if (S0 >= PRE && S1 < PRE) sB1 = 4 * t + 0;
    __syncthreads();
    if (t == 0) g_B1[b] = sB1;
}

// -------- kernel 3: grid-wide gather with direct bin-segment placement ----------
__global__ void __launch_bounds__(256) gatherk_kernel() {
    int b = blockIdx.y;
    int j4 = blockIdx.x * 256 + threadIdx.x;
    if (j4 >= NANCH / 4) return;
    int B1 = g_B1[b];
    const float4* sp = (const float4*)(g_scores + (size_t)b * NANCH);
    float4 v4 = sp[j4];                        // NANCH % 4 == 0
    float vv[4] = {v4.x, v4.y, v4.z, v4.w};
#pragma unroll
    for (int c = 0; c < 4; c++) {
        float v = vv[c];
        if (v > 0.0f) {
            int bin = (int)(v * 4096.0f); bin = bin > 4095 ? 4095 : bin;
            if (bin >= B1) {
                unsigned j = 4 * j4 + c;
                unsigned long long key =
                    ((unsigned long long)__float_as_uint(v) << 32) |
                    (unsigned long long)(0xFFFFFFFFu - j);
                unsigned pos = g_segbase[b * BINS + bin] +
                               atomicAdd(&g_hist[b * BINS + bin], 1u);
                if (pos < PRE2) g_keys[b * PRE2 + pos] = key;
            }
        }
    }
}

// ---- small warp bitonic-128 (descending), 4 u64/lane, fully unrolled (~5KB) ----
__device__ __forceinline__ void warp_bitonic128_desc(unsigned long long v[4], int lane) {
#pragma unroll
    for (unsigned k = 2; k <= 128; k <<= 1) {
#pragma unroll
        for (unsigned j = k >> 1; j > 0; j >>= 1) {
            if (j >= 32) {
                const int es = (int)(j >> 5);          // 1 or 2, compile-time
#pragma unroll
                for (int e = 0; e < 4; e++) {
                    const int pe = e ^ es;
                    if (pe > e) {
                        unsigned i = (unsigned)(e * 32 + lane);
                        bool keepmax = ((i & k) == 0);
                        unsigned long long a = v[e], bb = v[pe];
                        unsigned long long hi = a > bb ? a : bb;
                        unsigned long long lo = a > bb ? bb : a;
                        v[e]  = keepmax ? hi : lo;
                        v[pe] = keepmax ? lo : hi;
                    }
                }
            } else {
#pragma unroll
                for (int e = 0; e < 4; e++) {
                    unsigned long long p = __shfl_xor_sync(0xffffffffu, v[e], j);
                    unsigned i = (unsigned)(e * 32 + lane);
                    bool keepmax = ((i & k) == 0) == ((i & j) == 0);
                    bool kmax = keepmax ? (v[e] < p) : (v[e] > p);
                    v[e] = kmax ? p : v[e];
                }
            }
        }
    }
}

// -------- kernel 4: per-segment warp sorts + emit (self-cleans counters) --------
// Segments (bins) are strictly score-ordered; concatenation of descending
// per-segment sorts == full descending sort of all gathered keys.
__global__ void __launch_bounds__(256) sortg_kernel() {
    int b = blockIdx.x, t = threadIdx.x;
    int lane = t & 31, wid = t >> 5;
    __shared__ unsigned sTotal;
    int B1 = g_B1[b];
    if (t == 0) {
        unsigned total = g_segbase[b * BINS + B1] + g_hist[b * BINS + B1];
        sTotal = total < PRE ? total : PRE;
    }
    __syncthreads();

    for (int bin = B1 + wid; bin < BINS; bin += 8) {
        unsigned cnt = g_hist[b * BINS + bin];      // warp-uniform broadcast load
        if (cnt == 0) continue;
        if (lane == 0) g_hist[b * BINS + bin] = 0;  // self-clean
        unsigned base = g_segbase[b * BINS + bin];  // < PRE always
        unsigned L = cnt < SEGCAP ? cnt : SEGCAP;
        if (L <= 1) continue;                        // single key already in place
        unsigned long long v[4];
#pragma unroll
        for (int e = 0; e < 4; e++) {
            unsigned i = (unsigned)(e * 32 + lane);
            v[e] = (i < L) ? g_keys[b * PRE2 + base + i] : 0ull;
        }
        warp_bitonic128_desc(v, lane);
#pragma unroll
        for (int e = 0; e < 4; e++) {
            unsigned i = (unsigned)(e * 32 + lane);
            if (i < L) g_keys[b * PRE2 + base + i] = v[e];
        }
    }
    __syncthreads();

    unsigned total = sTotal;
    for (int i = t; i < PRE; i += 256) {
        unsigned long long kk = (i < (int)total) ? g_keys[b * PRE2 + i] : 0ull;
        g_selscore[b * PRE + i] = __uint_as_float((unsigned)(kk >> 32));
        g_selidx[b * PRE + i]   = (int)(0xFFFFFFFFu - (unsigned)(kk & 0xFFFFFFFFu));
    }
}

// ---------------- kernel 5: grid-wide box + argmax-class gather ----------------
__global__ void __launch_bounds__(128) gatherbx_kernel(const float* __restrict__ pred) {
    int i = blockIdx.x * 128 + threadIdx.x;
    if (i >= BATCH * PRE) return;
    int b = i >> 10;
    int idx = g_selidx[i];
    int ai = ((unsigned)idx < NANCH) ? idx : 0;     // zero-pad entries (score 0)
    const float4* p = (const float4*)(pred + ((size_t)b * NANCH + ai) * STRIDE);
    float4 xywh = p[0];
    float hw = __fmul_rn(xywh.z, 0.5f), hh = __fmul_rn(xywh.w, 0.5f);
    float4 bx;
    bx.x = __fsub_rn(xywh.x, hw); bx.y = __fsub_rn(xywh.y, hh);
    bx.z = __fadd_rn(xywh.x, hw); bx.w = __fadd_rn(xywh.y, hh);
    ((float4*)g_boxes)[i] = bx;
    // argmax over obj*cls, first-max semantics (class c at word 5+c)
    float4 r0 = p[1];                 // words 4..7: obj, cls0, cls1, cls2
    float obj = r0.x;
    int best = 0; float bv = __fmul_rn(r0.y, obj);
    { float v1 = __fmul_rn(r0.z, obj); if (v1 > bv) { bv = v1; best = 1; }
      float v2 = __fmul_rn(r0.w, obj); if (v2 > bv) { bv = v2; best = 2; } }
#pragma unroll
    for (int q = 2; q <= 9; q++) {
        float4 rq = p[q];             // words 4q..4q+3 -> classes 4q-5 .. 4q-2
        int cb = 4 * q - 5;
        float v0 = __fmul_rn(rq.x, obj); if (v0 > bv) { bv = v0; best = cb + 0; }
        float v1 = __fmul_rn(rq.y, obj); if (v1 > bv) { bv = v1; best = cb + 1; }
        float v2 = __fmul_rn(rq.z, obj); if (v2 > bv) { bv = v2; best = cb + 2; }
        float v3 = __fmul_rn(rq.w, obj); if (v3 > bv) { bv = v3; best = cb + 3; }
    }
    g_cls[i] = (float)best;
}

// ---------------- kernel 6: IoU bitmask (skewed SoA smem, gated div) ----------
__global__ void __launch_bounds__(256) iou_kernel() {
    int b = blockIdx.y;
    int warp = threadIdx.x >> 5, lane = threadIdx.x & 31;
    int r = blockIdx.x * 8 + warp;
    __shared__ float sx1[1056], sy1[1056], sx2[1056], sy2[1056], sar[1056];
    for (int j = threadIdx.x; j < PRE; j += 256) {
        float4 v = ((const float4*)g_boxes)[b * PRE + j];
        int jj = j + (j >> 5);                 // skew: lane-stride-32 -> conflict-free
        sx1[jj] = v.x; sy1[jj] = v.y; sx2[jj] = v.z; sy2[jj] = v.w;
        float w0 = fmaxf(__fsub_rn(v.z, v.x), 0.0f);
        float h0 = fmaxf(__fsub_rn(v.w, v.y), 0.0f);
        sar[jj] = __fmul_rn(w0, h0);
    }
    __syncthreads();
    int rr = r + (r >> 5);
    float bx1 = sx1[rr], by1 = sy1[rr], bx2 = sx2[rr], by2 = sy2[rr], ar = sar[rr];
    unsigned word = 0u;
    int jbase = lane * 32;
    if (jbase + 31 > r) {
        int jjb = lane * 33;
#pragma unroll
        for (int k = 0; k < 32; k++) {
            int j = jbase + k;
            if (j > r) {
                float lx = fmaxf(bx1, sx1[jjb + k]), ly = fmaxf(by1, sy1[jjb + k]);
                float rx = fminf(bx2, sx2[jjb + k]), ry = fminf(by2, sy2[jjb + k]);
                float iw = fmaxf(__fsub_rn(rx, lx), 0.0f);
                float ih = fmaxf(__fsub_rn(ry, ly), 0.0f);
                float inter = __fmul_rn(iw, ih);
                if (inter > 0.0f) {            // iou==0 can't exceed 0.45
                    float aj = sar[jjb + k];
                    float denom = __fadd_rn(__fsub_rn(__fadd_rn(ar, aj), inter), 1e-7f);
                    if ((inter / denom) > IOU_T) word |= (1u << k);
                }
            }
        }
    }
    g_mask[((size_t)b * PRE + r) * 32 + lane] = word;
}

// ---------------- kernel 7: NMS scan over smem-staged masks + top-300 out -------
__global__ void __launch_bounds__(256) nms_kernel(float* __restrict__ out) {
    extern __shared__ unsigned sh[];
    unsigned* smask  = sh;                          // PRE*32 words (128 KB)
    float*    sscore = (float*)(sh + PRE * 32);     // PRE floats
    __shared__ unsigned svalid[32];
    __shared__ unsigned skeep[32];
    __shared__ unsigned kpre[33];
    int b = blockIdx.x, t = threadIdx.x;

    // stage masks (coalesced uint4) + scores/validity
    const uint4* gm4 = (const uint4*)(g_mask + (size_t)b * PRE * 32);
    uint4* sm4 = (uint4*)smask;
    for (int j = t; j < PRE * 8; j += 256) sm4[j] = gm4[j];
    for (int it = 0; it < 4; it++) {
        int e = it * 256 + t;
        float sc = g_selscore[b * PRE + e];
        sscore[e] = sc;
        unsigned bl = __ballot_sync(0xffffffffu, sc > 0.0f);
        if ((t & 31) == 0) svalid[it * 8 + (t >> 5)] = bl;
    }
    __syncthreads();

    // warp 0: word-parallel scan (lane = distributed suppression word)
    if (t < 32) {
        unsigned sup = 0u, mykeep = 0u;
        for (int w = 0; w < 32; w++) {
            unsigned m[32];
#pragma unroll
            for (int k = 0; k < 32; k++) m[k] = smask[(w * 32 + k) * 32 + t];
            unsigned kw = 0u;
            if (t == w) {
                unsigned ss = sup, vw = svalid[w];
#pragma unroll
                for (int k = 0; k < 32; k++) {
                    unsigned bit = 1u << k;
                    if ((vw & bit) && !(ss & bit)) { kw |= bit; ss |= m[k]; }
                }
                sup = ss;
            }
            kw = __shfl_sync(0xffffffffu, kw, w);
            if (t == w) {
                mykeep = kw;
            } else {
#pragma unroll
                for (int k = 0; k < 32; k++)
                    if (kw & (1u << k)) sup |= m[k];
            }
        }
        skeep[t] = mykeep;
    }
    __syncthreads();

    if (t < 32) {
        unsigned acc = 0;
        for (int q = 0; q < 32; q++) {
            if (q == t) kpre[t] = acc;
            acc += __popc(skeep[q]);
        }
        if (t == 31) kpre[32] = acc;
    }
    __syncthreads();
    unsigned total = kpre[32];

    for (int e = t; e < PRE; e += 256) {
        int w = e >> 5, bit = e & 31;
        int rank = kpre[w] + __popc(skeep[w] & ((1u << bit) - 1u));
        bool kp = (skeep[w] >> bit) & 1u;
        int orow = -1; float osc = 0.0f;
        if (kp) {
            if (rank < MAXD) { orow = rank; osc = sscore[e]; }
        } else {
            int nr = e - rank;
            if ((int)total + nr < MAXD) orow = (int)total + nr;
        }
        if (orow >= 0) {
            float4 bx = ((const float4*)g_boxes)[b * PRE + e];
            float cc = g_cls[b * PRE + e];
            float* o = out + ((size_t)b * MAXD + orow) * 6;
            o[0] = bx.x; o[1] = bx.y; o[2] = bx.z; o[3] = bx.w;
            o[4] = osc;  o[5] = cc;
        }
    }
}

// ---------------- launch ----------------
extern "C" void kernel_launch(void* const* d_in, const int* in_sizes, int n_in,
                              void* d_out, int out_size) {
    const float* pred = (const float*)d_in[0];
    float* out = (float*)d_out;

    const int nms_smem = (PRE * 32 + PRE) * 4;      // 135168 bytes
    cudaFuncSetAttribute(nms_kernel, cudaFuncAttributeMaxDynamicSharedMemorySize, nms_smem);

    score_kernel<<<dim3((NANCH + 255) / 256, BATCH), 256>>>(pred);
    thresh_kernel<<<BATCH, 1024>>>();
    gatherk_kernel<<<dim3((NANCH / 4 + 255) / 256, BATCH), 256>>>();
    sortg_kernel<<<BATCH, 256>>>();
    gatherbx_kernel<<<(BATCH * PRE) / 128, 128>>>(pred);
    iou_kernel<<<dim3(PRE / 8, BATCH), 256>>>();
    nms_kernel<<<BATCH, 256, nms_smem>>>(out);
}

// round 16
// speedup vs baseline: 1.0190x; 1.0190x over previous
#include <cuda_runtime.h>
#include <cstdint>

#define BATCH   16
#define NANCH   102000
#define NCLS    35
#define STRIDE  40          // 4 box + 1 obj + 35 cls
#define PRE     1024
#define PRE2    2048        // keys array stride per batch (slack for boundary bin)
#define MAXD    300
#define CONF_T  0.25f
#define IOU_T   0.45f
#define BINS    4096
#define SEGCAP  128         // max keys per bin segment the warp sort handles
#define WLCAP   1024        // worklist capacity (bins with >=2 keys <= (PRE+SEGCAP)/2)

// ---------------- device scratch (all self-cleaning across graph replays) -------
__device__ __align__(16) float    g_scores[BATCH * NANCH];
__device__ __align__(16) unsigned g_hist[BATCH * BINS];     // zeroed by thresh, reused as
                                                            // placement counters, zeroed by sortg
__device__ __align__(16) unsigned g_segbase[BATCH * BINS];  // suffix sums (rewritten each run)
__device__ __align__(16) int      g_B1[BATCH];
__device__ __align__(16) unsigned long long g_keys[BATCH * PRE2];
__device__ __align__(16) int      g_selidx[BATCH * PRE];
__device__ __align__(16) float    g_selscore[BATCH * PRE];
__device__ __align__(16) float    g_boxes[BATCH * PRE * 4];
__device__ __align__(16) float    g_cls[BATCH * PRE];
__device__ __align__(16) unsigned g_mask[BATCH * PRE * 32];

// ---------------- kernel 1: score + histogram (smem-staged, coalesced) ----------
__global__ void __launch_bounds__(256) score_kernel(const float* __restrict__ pred) {
    __shared__ float st[256 * 41];              // 41-float stride: conflict-free reads
    int b = blockIdx.y;
    int a0 = blockIdx.x * 256;
    int nrem = NANCH - a0; if (nrem > 256) nrem = 256;
    const float4* gp = (const float4*)(pred + ((size_t)b * NANCH + a0) * STRIDE);
    int nv4 = nrem * 10;                        // 10 float4 per anchor
    for (int g = threadIdx.x; g < nv4; g += 256) {
        float4 v = gp[g];
        int anchor = g / 10;
        int ew = (g - anchor * 10) * 4;
        float* d = st + anchor * 41 + ew;
        d[0] = v.x; d[1] = v.y; d[2] = v.z; d[3] = v.w;
    }
    __syncthreads();
    int t = threadIdx.x;
    if (t < nrem) {
        const float* s = st + t * 41;
        float obj = s[4];
        float conf = 0.0f;
#pragma unroll
        for (int c = 0; c < NCLS; c++)
            conf = fmaxf(conf, __fmul_rn(s[5 + c], obj));
        float sc = (obj > CONF_T && conf > CONF_T) ? conf : 0.0f;
        g_scores[(size_t)b * NANCH + a0 + t] = sc;
        if (sc > 0.0f) {
            int bin = (int)(sc * 4096.0f); bin = bin > 4095 ? 4095 : bin;
            atomicAdd(&g_hist[b * BINS + bin], 1u);
        }
    }
}

// ------- kernel 2: threshold bin + per-bin segment bases (self-cleans hist) ------
__global__ void __launch_bounds__(1024) thresh_kernel() {
    int b = blockIdx.x, t = threadIdx.x;
    int lane = t & 31, w = t >> 5;
    __shared__ unsigned warpsum[32];
    __shared__ int sB1;
    uint4 h = ((const uint4*)(g_hist + b * BINS))[t];
    ((uint4*)(g_hist + b * BINS))[t] = make_uint4(0u, 0u, 0u, 0u);  // zero -> counters
    unsigned s = h.x + h.y + h.z + h.w;
    unsigned sacc = s;
#pragma unroll
    for (int o = 1; o < 32; o <<= 1) {
        unsigned v = __shfl_down_sync(0xffffffffu, sacc, o);
        if (lane + o < 32) sacc += v;
    }
    if (lane == 0) warpsum[w] = sacc;
    __syncthreads();
    if (t < 32) {
        unsigned ws = warpsum[t];
        unsigned wacc = ws;
#pragma unroll
        for (int o = 1; o < 32; o <<= 1) {
            unsigned v = __shfl_down_sync(0xffffffffu, wacc, o);
            if (t + o < 32) wacc += v;
        }
        warpsum[t] = wacc - ws;     // exclusive suffix over warps
    }
    __syncthreads();
    unsigned S_incl = sacc + warpsum[w];     // count(bins >= 4t)
    if (t == 0) sB1 = 0;                     // fallback: total < PRE -> take everything
    __syncthreads();
    unsigned S4 = S_incl - s;                // count(bins >= 4t+4) == base[4t+3]
    unsigned S3 = S4 + h.w;                  // base[4t+2]
    unsigned S2 = S3 + h.z;                  // base[4t+1]
    unsigned S1 = S2 + h.y;                  // base[4t+0]
    unsigned S0 = S1 + h.x;
    // per-bin suffix bases: segbase[bin] = count(bins' > bin)
    ((uint4*)(g_segbase + b * BINS))[t] = make_uint4(S1, S2, S3, S4);
    if (S3 >= PRE && S4 < PRE) sB1 = 4 * t + 3;
    if (S2 >= PRE && S3 < PRE) sB1 = 4 * t + 2;
    if (S1 >= PRE && S2 < PRE) sB1 = 4 * t + 1;
    if (S0 >= PRE && S1 < PRE) sB1 = 4 * t + 0;
    __syncthreads();
    if (t == 0) g_B1[b] = sB1;
}

// -------- kernel 3: grid-wide gather with direct bin-segment placement ----------
__global__ void __launch_bounds__(256) gatherk_kernel() {
    int b = blockIdx.y;
    int j4 = blockIdx.x * 256 + threadIdx.x;
    if (j4 >= NANCH / 4) return;
    int B1 = g_B1[b];
    const float4* sp = (const float4*)(g_scores + (size_t)b * NANCH);
    float4 v4 = sp[j4];                        // NANCH % 4 == 0
    float vv[4] = {v4.x, v4.y, v4.z, v4.w};
#pragma unroll
    for (int c = 0; c < 4; c++) {
        float v = vv[c];
        if (v > 0.0f) {
            int bin = (int)(v * 4096.0f); bin = bin > 4095 ? 4095 : bin;
            if (bin >= B1) {
                unsigned j = 4 * j4 + c;
                unsigned long long key =
                    ((unsigned long long)__float_as_uint(v) << 32) |
                    (unsigned long long)(0xFFFFFFFFu - j);
                unsigned pos = g_segbase[b * BINS + bin] +
                               atomicAdd(&g_hist[b * BINS + bin], 1u);
                if (pos < PRE2) g_keys[b * PRE2 + pos] = key;
            }
        }
    }
}

// ---- small warp bitonic-128 (descending), 4 u64/lane, fully unrolled (~5KB) ----
__device__ __forceinline__ void warp_bitonic128_desc(unsigned long long v[4], int lane) {
#pragma unroll
    for (unsigned k = 2; k <= 128; k <<= 1) {
#pragma unroll
        for (unsigned j = k >> 1; j > 0; j >>= 1) {
            if (j >= 32) {
                const int es = (int)(j >> 5);          // 1 or 2, compile-time
#pragma unroll
                for (int e = 0; e < 4; e++) {
                    const int pe = e ^ es;
                    if (pe > e) {
                        unsigned i = (unsigned)(e * 32 + lane);
                        bool keepmax = ((i & k) == 0);
                        unsigned long long a = v[e], bb = v[pe];
                        unsigned long long hi = a > bb ? a : bb;
                        unsigned long long lo = a > bb ? bb : a;
                        v[e]  = keepmax ? hi : lo;
                        v[pe] = keepmax ? lo : hi;
                    }
                }
            } else {
#pragma unroll
                for (int e = 0; e < 4; e++) {
                    unsigned long long p = __shfl_xor_sync(0xffffffffu, v[e], j);
                    unsigned i = (unsigned)(e * 32 + lane);
                    bool keepmax = ((i & k) == 0) == ((i & j) == 0);
                    bool take = keepmax ? (v[e] < p) : (v[e] > p);
                    v[e] = take ? p : v[e];
                }
            }
        }
    }
}

// ---- kernel 4: worklist-compacted per-segment sorts + emit (self-cleans hist) ----
// Segments (bins) are strictly score-ordered; concatenation of descending
// per-segment sorts == full descending sort of all gathered keys.
__global__ void __launch_bounds__(256) sortg_kernel() {
    int b = blockIdx.x, t = threadIdx.x;
    int lane = t & 31, wid = t >> 5;
    __shared__ unsigned swork[WLCAP];       // packed: (bin << 16) | cnt
    __shared__ unsigned snwork;
    __shared__ unsigned sTotal;
    int B1 = g_B1[b];
    if (t == 0) snwork = 0u;
    __syncthreads();

    // coalesced scan of hist[B1..BINS): compact bins needing a sort, self-clean.
    int nbins = BINS - B1;
    for (int i = t; i < nbins; i += 256) {
        int bin = B1 + i;
        unsigned cnt = g_hist[b * BINS + bin];       // independent loads, full MLP
        if (i == 0) {
            unsigned total = g_segbase[b * BINS + B1] + cnt;
            sTotal = total < PRE ? total : PRE;
        }
        if (cnt != 0) {
            g_hist[b * BINS + bin] = 0u;             // self-clean
            if (cnt > 1) {
                unsigned c = cnt < SEGCAP ? cnt : SEGCAP;
                unsigned pos = atomicAdd(&snwork, 1u);
                if (pos < WLCAP) swork[pos] = ((unsigned)bin << 16) | c;
            }
        }
    }
    __syncthreads();

    unsigned nwork = snwork; if (nwork > WLCAP) nwork = WLCAP;
    for (unsigned widx = wid; widx < nwork; widx += 8) {
        unsigned pk = swork[widx];
        unsigned bin = pk >> 16;
        unsigned L = pk & 0xFFFFu;
        unsigned base = g_segbase[b * BINS + bin];
        unsigned long long v[4];
#pragma unroll
        for (int e = 0; e < 4; e++) {
            unsigned i = (unsigned)(e * 32 + lane);
            v[e] = (i < L) ? g_keys[b * PRE2 + base + i] : 0ull;
        }
        warp_bitonic128_desc(v, lane);
#pragma unroll
        for (int e = 0; e < 4; e++) {
            unsigned i = (unsigned)(e * 32 + lane);
            if (i < L) g_keys[b * PRE2 + base + i] = v[e];
        }
    }
    __syncthreads();

    unsigned total = sTotal;
    for (int i = t; i < PRE; i += 256) {
        unsigned long long kk = (i < (int)total) ? g_keys[b * PRE2 + i] : 0ull;
        g_selscore[b * PRE + i] = __uint_as_float((unsigned)(kk >> 32));
        g_selidx[b * PRE + i]   = (int)(0xFFFFFFFFu - (unsigned)(kk & 0xFFFFFFFFu));
    }
}

// ---------------- kernel 5: grid-wide box + argmax-class gather ----------------
__global__ void __launch_bounds__(128) gatherbx_kernel(const float* __restrict__ pred) {
    int i = blockIdx.x * 128 + threadIdx.x;
    if (i >= BATCH * PRE) return;
    int b = i >> 10;
    int idx = g_selidx[i];
    int ai = ((unsigned)idx < NANCH) ? idx : 0;     // zero-pad entries (score 0)
    const float4* p = (const float4*)(pred + ((size_t)b * NANCH + ai) * STRIDE);
    float4 xywh = p[0];
    float hw = __fmul_rn(xywh.z, 0.5f), hh = __fmul_rn(xywh.w, 0.5f);
    float4 bx;
    bx.x = __fsub_rn(xywh.x, hw); bx.y = __fsub_rn(xywh.y, hh);
    bx.z = __fadd_rn(xywh.x, hw); bx.w = __fadd_rn(xywh.y, hh);
    ((float4*)g_boxes)[i] = bx;
    // argmax over obj*cls, first-max semantics (class c at word 5+c)
    float4 r0 = p[1];                 // words 4..7: obj, cls0, cls1, cls2
    float obj = r0.x;
    int best = 0; float bv = __fmul_rn(r0.y, obj);
    { float v1 = __fmul_rn(r0.z, obj); if (v1 > bv) { bv = v1; best = 1; }
      float v2 = __fmul_rn(r0.w, obj); if (v2 > bv) { bv = v2; best = 2; } }
#pragma unroll
    for (int q = 2; q <= 9; q++) {
        float4 rq = p[q];             // words 4q..4q+3 -> classes 4q-5 .. 4q-2
        int cb = 4 * q - 5;
        float v0 = __fmul_rn(rq.x, obj); if (v0 > bv) { bv = v0; best = cb + 0; }
        float v1 = __fmul_rn(rq.y, obj); if (v1 > bv) { bv = v1; best = cb + 1; }
        float v2 = __fmul_rn(rq.z, obj); if (v2 > bv) { bv = v2; best = cb + 2; }
        float v3 = __fmul_rn(rq.w, obj); if (v3 > bv) { bv = v3; best = cb + 3; }
    }
    g_cls[i] = (float)best;
}

// ---------------- kernel 6: IoU bitmask (skewed SoA smem, gated div) ----------
__global__ void __launch_bounds__(256) iou_kernel() {
    int b = blockIdx.y;
    int warp = threadIdx.x >> 5, lane = threadIdx.x & 31;
    int r = blockIdx.x * 8 + warp;
    __shared__ float sx1[1056], sy1[1056], sx2[1056], sy2[1056], sar[1056];
    for (int j = threadIdx.x; j < PRE; j += 256) {
        float4 v = ((const float4*)g_boxes)[b * PRE + j];
        int jj = j + (j >> 5);                 // skew: lane-stride-32 -> conflict-free
        sx1[jj] = v.x; sy1[jj] = v.y; sx2[jj] = v.z; sy2[jj] = v.w;
        float w0 = fmaxf(__fsub_rn(v.z, v.x), 0.0f);
        float h0 = fmaxf(__fsub_rn(v.w, v.y), 0.0f);
        sar[jj] = __fmul_rn(w0, h0);
    }
    __syncthreads();
    int rr = r + (r >> 5);
    float bx1 = sx1[rr], by1 = sy1[rr], bx2 = sx2[rr], by2 = sy2[rr], ar = sar[rr];
    unsigned word = 0u;
    int jbase = lane * 32;
    if (jbase + 31 > r) {
        int jjb = lane * 33;
#pragma unroll
        for (int k = 0; k < 32; k++) {
            int j = jbase + k;
            if (j > r) {
                float lx = fmaxf(bx1, sx1[jjb + k]), ly = fmaxf(by1, sy1[jjb + k]);
                float rx = fminf(bx2, sx2[jjb + k]), ry = fminf(by2, sy2[jjb + k]);
                float iw = fmaxf(__fsub_rn(rx, lx), 0.0f);
                float ih = fmaxf(__fsub_rn(ry, ly), 0.0f);
                float inter = __fmul_rn(iw, ih);
                if (inter > 0.0f) {            // iou==0 can't exceed 0.45
                    float aj = sar[jjb + k];
                    float denom = __fadd_rn(__fsub_rn(__fadd_rn(ar, aj), inter), 1e-7f);
                    if ((inter / denom) > IOU_T) word |= (1u << k);
                }
            }
        }
    }
    g_mask[((size_t)b * PRE + r) * 32 + lane] = word;
}

// ---------------- kernel 7: NMS scan over smem-staged masks + top-300 out -------
__global__ void __launch_bounds__(256) nms_kernel(float* __restrict__ out) {
    extern __shared__ unsigned sh[];
    unsigned* smask  = sh;                          // PRE*32 words (128 KB)
    float*    sscore = (float*)(sh + PRE * 32);     // PRE floats
    __shared__ unsigned svalid[32];
    __shared__ unsigned skeep[32];
    __shared__ unsigned kpre[33];
    int b = blockIdx.x, t = threadIdx.x;

    // stage masks (coalesced uint4) + scores/validity
    const uint4* gm4 = (const uint4*)(g_mask + (size_t)b * PRE * 32);
    uint4* sm4 = (uint4*)smask;
    for (int j = t; j < PRE * 8; j += 256) sm4[j] = gm4[j];
    for (int it = 0; it < 4; it++) {
        int e = it * 256 + t;
        float sc = g_selscore[b * PRE + e];
        sscore[e] = sc;
        unsigned bl = __ballot_sync(0xffffffffu, sc > 0.0f);
        if ((t & 31) == 0) svalid[it * 8 + (t >> 5)] = bl;
    }
    __syncthreads();

    // warp 0: word-parallel scan (lane = distributed suppression word)
    if (t < 32) {
        unsigned sup = 0u, mykeep = 0u;
        for (int w = 0; w < 32; w++) {
            unsigned m[32];
#pragma unroll
            for (int k = 0; k < 32; k++) m[k] = smask[(w * 32 + k) * 32 + t];
            unsigned kw = 0u;
            if (t == w) {
                unsigned ss = sup, vw = svalid[w];
#pragma unroll
                for (int k = 0; k < 32; k++) {
                    unsigned bit = 1u << k;
                    if ((vw & bit) && !(ss & bit)) { kw |= bit; ss |= m[k]; }
                }
                sup = ss;
            }
            kw = __shfl_sync(0xffffffffu, kw, w);
            if (t == w) {
                mykeep = kw;
            } else {
#pragma unroll
                for (int k = 0; k < 32; k++)
                    if (kw & (1u << k)) sup |= m[k];
            }
        }
        skeep[t] = mykeep;
    }
    __syncthreads();

    if (t < 32) {
        unsigned acc = 0;
        for (int q = 0; q < 32; q++) {
            if (q == t) kpre[t] = acc;
            acc += __popc(skeep[q]);
        }
        if (t == 31) kpre[32] = acc;
    }
    __syncthreads();
    unsigned total = kpre[32];

    for (int e = t; e < PRE; e += 256) {
        int w = e >> 5, bit = e & 31;
        int rank = kpre[w] + __popc(skeep[w] & ((1u << bit) - 1u));
        bool kp = (skeep[w] >> bit) & 1u;
        int orow = -1; float osc = 0.0f;
        if (kp) {
            if (rank < MAXD) { orow = rank; osc = sscore[e]; }
        } else {
            int nr = e - rank;
            if ((int)total + nr < MAXD) orow = (int)total + nr;
        }
        if (orow >= 0) {
            float4 bx = ((const float4*)g_boxes)[b * PRE + e];
            float cc = g_cls[b * PRE + e];
            float* o = out + ((size_t)b * MAXD + orow) * 6;
            o[0] = bx.x; o[1] = bx.y; o[2] = bx.z; o[3] = bx.w;
            o[4] = osc;  o[5] = cc;
        }
    }
}

// ---------------- launch ----------------
extern "C" void kernel_launch(void* const* d_in, const int* in_sizes, int n_in,
                              void* d_out, int out_size) {
    const float* pred = (const float*)d_in[0];
    float* out = (float*)d_out;

    const int nms_smem = (PRE * 32 + PRE) * 4;      // 135168 bytes
    cudaFuncSetAttribute(nms_kernel, cudaFuncAttributeMaxDynamicSharedMemorySize, nms_smem);

    score_kernel<<<dim3((NANCH + 255) / 256, BATCH), 256>>>(pred);
    thresh_kernel<<<BATCH, 1024>>>();
    gatherk_kernel<<<dim3((NANCH / 4 + 255) / 256, BATCH), 256>>>();
    sortg_kernel<<<BATCH, 256>>>();
    gatherbx_kernel<<<(BATCH * PRE) / 128, 128>>>(pred);
    iou_kernel<<<dim3(PRE / 8, BATCH), 256>>>();
    nms_kernel<<<BATCH, 256, nms_smem>>>(out);
}

// round 17
// speedup vs baseline: 1.7487x; 1.7161x over previous
#include <cuda_runtime.h>
#include <cstdint>

#define BATCH   16
#define NANCH   102000
#define NCLS    35
#define STRIDE  40          // 4 box + 1 obj + 35 cls
#define PRE     1024
#define MAXD    300
#define CONF_T  0.25f
#define IOU_T   0.45f
#define BINS    4096

// ---------------- device scratch (all self-cleaning across graph replays) -------
__device__ __align__(16) float    g_scores[BATCH * NANCH];
__device__ __align__(16) unsigned g_hist[BATCH * BINS];   // zeroed by thresh_kernel
__device__ __align__(16) int      g_B1[BATCH];
__device__ __align__(16) unsigned g_G[BATCH];
__device__ __align__(16) unsigned g_cnt[BATCH * 2];       // zeroed by sortg_kernel
__device__ __align__(16) unsigned long long g_keys[BATCH * PRE];
__device__ __align__(16) unsigned long long g_eqkeys[BATCH * PRE];
__device__ __align__(16) float    g_selscore[BATCH * PRE];
__device__ __align__(16) float    g_boxes[BATCH * PRE * 4];
__device__ __align__(16) float    g_cls[BATCH * PRE];
__device__ __align__(16) unsigned g_mask[BATCH * PRE * 32];

// ---------------- kernel 1: score + histogram (smem-staged, coalesced) ----------
__global__ void __launch_bounds__(256) score_kernel(const float* __restrict__ pred) {
    __shared__ float st[256 * 41];              // 41-float stride: conflict-free reads
    int b = blockIdx.y;
    int a0 = blockIdx.x * 256;
    int nrem = NANCH - a0; if (nrem > 256) nrem = 256;
    const float4* gp = (const float4*)(pred + ((size_t)b * NANCH + a0) * STRIDE);
    int nv4 = nrem * 10;                        // 10 float4 per anchor
    for (int g = threadIdx.x; g < nv4; g += 256) {
        float4 v = gp[g];
        int anchor = g / 10;
        int ew = (g - anchor * 10) * 4;
        float* d = st + anchor * 41 + ew;
        d[0] = v.x; d[1] = v.y; d[2] = v.z; d[3] = v.w;
    }
    __syncthreads();
    int t = threadIdx.x;
    if (t < nrem) {
        const float* s = st + t * 41;
        float obj = s[4];
        float conf = 0.0f;
#pragma unroll
        for (int c = 0; c < NCLS; c++)
            conf = fmaxf(conf, __fmul_rn(s[5 + c], obj));
        float sc = (obj > CONF_T && conf > CONF_T) ? conf : 0.0f;
        g_scores[(size_t)b * NANCH + a0 + t] = sc;
        if (sc > 0.0f) {
            int bin = (int)(sc * 4096.0f); bin = bin > 4095 ? 4095 : bin;
            atomicAdd(&g_hist[b * BINS + bin], 1u);
        }
    }
}

// ---------------- kernel 2: threshold bin per batch (self-cleans hist) ----------
__global__ void __launch_bounds__(1024) thresh_kernel() {
    int b = blockIdx.x, t = threadIdx.x;
    int lane = t & 31, w = t >> 5;
    __shared__ unsigned warpsum[32];
    __shared__ int sB1;
    __shared__ unsigned sG;
    uint4 h = ((const uint4*)(g_hist + b * BINS))[t];
    ((uint4*)(g_hist + b * BINS))[t] = make_uint4(0u, 0u, 0u, 0u);  // self-clean
    unsigned s = h.x + h.y + h.z + h.w;
    unsigned sacc = s;
#pragma unroll
    for (int o = 1; o < 32; o <<= 1) {
        unsigned v = __shfl_down_sync(0xffffffffu, sacc, o);
        if (lane + o < 32) sacc += v;
    }
    if (lane == 0) warpsum[w] = sacc;
    __syncthreads();
    if (t < 32) {
        unsigned ws = warpsum[t];
        unsigned wacc = ws;
#pragma unroll
        for (int o = 1; o < 32; o <<= 1) {
            unsigned v = __shfl_down_sync(0xffffffffu, wacc, o);
            if (t + o < 32) wacc += v;
        }
        warpsum[t] = wacc - ws;     // exclusive suffix over warps
    }
    __syncthreads();
    unsigned S_incl = sacc + warpsum[w];     // count(bins >= 4t)
    if (t == 0) { sB1 = 0; sG = (S_incl < PRE) ? S_incl : 0u; }
    __syncthreads();
    {
        unsigned S4 = S_incl - s;            // count(bins >= 4t+4)
        unsigned S3 = S4 + h.w, S2 = S3 + h.z, S1 = S2 + h.y, S0 = S1 + h.x;
        if (S3 >= PRE && S4 < PRE) { sB1 = 4 * t + 3; sG = S4; }
        if (S2 >= PRE && S3 < PRE) { sB1 = 4 * t + 2; sG = S3; }
        if (S1 >= PRE && S2 < PRE) { sB1 = 4 * t + 1; sG = S2; }
        if (S0 >= PRE && S1 < PRE) { sB1 = 4 * t + 0; sG = S1; }
    }
    __syncthreads();
    if (t == 0) { g_B1[b] = sB1; g_G[b] = sG; }
}

// ---------------- kernel 3: grid-wide candidate gather (atomic append) ----------
__global__ void __launch_bounds__(256) gatherk_kernel() {
    int b = blockIdx.y;
    int j4 = blockIdx.x * 256 + threadIdx.x;
    if (j4 >= (NANCH + 3) / 4) return;
    int B1 = g_B1[b];
    const float4* sp = (const float4*)(g_scores + (size_t)b * NANCH);
    float4 v4 = sp[j4];                        // NANCH % 4 == 0
    float vv[4] = {v4.x, v4.y, v4.z, v4.w};
#pragma unroll
    for (int c = 0; c < 4; c++) {
        float v = vv[c];
        if (v > 0.0f) {
            int bin = (int)(v * 4096.0f); bin = bin > 4095 ? 4095 : bin;
            if (bin >= B1) {
                unsigned j = 4 * j4 + c;
                unsigned long long key =
                    ((unsigned long long)__float_as_uint(v) << 32) |
                    (unsigned long long)(0xFFFFFFFFu - j);
                if (bin > B1) {
                    unsigned pos = atomicAdd(&g_cnt[b * 2], 1u);
                    if (pos < PRE) g_keys[b * PRE + pos] = key;
                } else {
                    unsigned pos = atomicAdd(&g_cnt[b * 2 + 1], 1u);
                    if (pos < PRE) g_eqkeys[b * PRE + pos] = key;
                }
            }
        }
    }
}

// ---------------- register-resident bitonic sort (descending, 1024 u64) ----------
__device__ __forceinline__ unsigned long long bmerge(unsigned long long v,
                                                     unsigned long long p,
                                                     bool keepmax) {
    return keepmax ? (v > p ? v : p) : (v < p ? v : p);
}

__device__ unsigned long long bitonic1024_desc(unsigned long long* a, int t) {
    unsigned long long v = a[t];
#pragma unroll
    for (unsigned k = 2; k <= 32; k <<= 1) {
#pragma unroll
        for (unsigned j = k >> 1; j > 0; j >>= 1) {
            unsigned long long p = __shfl_xor_sync(0xffffffffu, v, j);
            bool keepmax = ((t & k) == 0) == ((t & j) == 0);
            v = bmerge(v, p, keepmax);
        }
    }
    for (unsigned k = 64; k <= 1024; k <<= 1) {
        for (unsigned j = k >> 1; j >= 32; j >>= 1) {
            __syncthreads();
            a[t] = v;
            __syncthreads();
            unsigned long long p = a[t ^ j];
            bool keepmax = ((t & k) == 0) == ((t & j) == 0);
            v = bmerge(v, p, keepmax);
        }
#pragma unroll
        for (unsigned j = 16; j > 0; j >>= 1) {
            unsigned long long p = __shfl_xor_sync(0xffffffffu, v, j);
            bool keepmax = ((t & k) == 0) == ((t & j) == 0);
            v = bmerge(v, p, keepmax);
        }
    }
    __syncthreads();
    a[t] = v;
    __syncthreads();
    return v;
}

// ---- single-warp register bitonic-256 (descending), 8 elems/lane, no barriers ----
// element index i = e*32 + lane; j<32 -> shfl partner, j>=32 -> in-thread exchange
__device__ __forceinline__ void warp_bitonic256_desc(unsigned long long v[8], int lane) {
    for (unsigned k = 2; k <= 256; k <<= 1) {
        for (unsigned j = k >> 1; j > 0; j >>= 1) {
            if (j >= 32) {
                int es = (int)(j >> 5);
#pragma unroll
                for (int e = 0; e < 8; e++) {
                    int pe = e ^ es;
                    if (pe > e) {               // e has j-bit 0 -> (i&j)==0
                        unsigned i = (unsigned)(e * 32 + lane);
                        bool keepmax = ((i & k) == 0);
                        unsigned long long a = v[e], bb = v[pe];
                        unsigned long long hi = a > bb ? a : bb;
                        unsigned long long lo = a > bb ? bb : a;
                        v[e]  = keepmax ? hi : lo;
                        v[pe] = keepmax ? lo : hi;
                    }
                }
            } else {
#pragma unroll
                for (int e = 0; e < 8; e++) {
                    unsigned long long p = __shfl_xor_sync(0xffffffffu, v[e], j);
                    unsigned i = (unsigned)(e * 32 + lane);
                    bool keepmax = ((i & k) == 0) == ((i & j) == 0);
                    v[e] = bmerge(v[e], p, keepmax);
                }
            }
        }
    }
}

// ---------------- kernel 4: sort + box/cls gather (self-cleans counters) --------
__global__ void __launch_bounds__(1024) sortg_kernel(const float* __restrict__ pred) {
    int b = blockIdx.x, t = threadIdx.x;
    __shared__ unsigned long long keys[PRE];
    __shared__ unsigned long long eq[PRE];
    unsigned G = g_G[b]; if (G > PRE) G = PRE;
    unsigned eqc = g_cnt[b * 2 + 1]; if (eqc > PRE) eqc = PRE;
    keys[t] = (t < (int)G) ? g_keys[b * PRE + t] : 0ull;
    eq[t]   = (t < (int)eqc) ? g_eqkeys[b * PRE + t] : 0ull;
    if (t == 0) { g_cnt[b * 2] = 0u; g_cnt[b * 2 + 1] = 0u; }   // self-clean
    __syncthreads();

    // sort the boundary-bin keys descending.
    // common case (eqc <= 256): single-warp register sort, no block barriers.
    // note G + eqc >= PRE, so need = PRE-G <= eqc <= 256 is guaranteed to fit.
    if (eqc <= 256) {
        if (t < 32) {
            unsigned long long v[8];
#pragma unroll
            for (int e = 0; e < 8; e++) v[e] = eq[e * 32 + t];
            warp_bitonic256_desc(v, t);
#pragma unroll
            for (int e = 0; e < 8; e++) eq[e * 32 + t] = v[e];
        }
        __syncthreads();
    } else {
        bitonic1024_desc(eq, t);
    }

    unsigned need = PRE - G;
    if (t < (int)need) keys[G + t] = eq[t];
    __syncthreads();
    unsigned long long kk = bitonic1024_desc(keys, t);

    float sc = __uint_as_float((unsigned)(kk >> 32));
    unsigned idxu = 0xFFFFFFFFu - (unsigned)(kk & 0xFFFFFFFFu);
    int ai = (idxu < NANCH) ? (int)idxu : 0;
    g_selscore[b * PRE + t] = sc;
    const float4* p = (const float4*)(pred + ((size_t)b * NANCH + ai) * STRIDE);
    float4 xywh = p[0];
    float hw = __fmul_rn(xywh.z, 0.5f), hh = __fmul_rn(xywh.w, 0.5f);
    float4 bx;
    bx.x = __fsub_rn(xywh.x, hw); bx.y = __fsub_rn(xywh.y, hh);
    bx.z = __fadd_rn(xywh.x, hw); bx.w = __fadd_rn(xywh.y, hh);
    ((float4*)g_boxes)[b * PRE + t] = bx;
    // argmax over obj*cls, first-max semantics (class c at word 5+c)
    float4 r0 = p[1];                 // words 4..7: obj, cls0, cls1, cls2
    float obj = r0.x;
    int best = 0; float bv = __fmul_rn(r0.y, obj);
    { float v1 = __fmul_rn(r0.z, obj); if (v1 > bv) { bv = v1; best = 1; }
      float v2 = __fmul_rn(r0.w, obj); if (v2 > bv) { bv = v2; best = 2; } }
#pragma unroll
    for (int q = 2; q <= 9; q++) {
        float4 rq = p[q];             // words 4q..4q+3 -> classes 4q-5 .. 4q-2
        int cb = 4 * q - 5;
        float v0 = __fmul_rn(rq.x, obj); if (v0 > bv) { bv = v0; best = cb + 0; }
        float v1 = __fmul_rn(rq.y, obj); if (v1 > bv) { bv = v1; best = cb + 1; }
        float v2 = __fmul_rn(rq.z, obj); if (v2 > bv) { bv = v2; best = cb + 2; }
        float v3 = __fmul_rn(rq.w, obj); if (v3 > bv) { bv = v3; best = cb + 3; }
    }
    g_cls[b * PRE + t] = (float)best;
}

// ------ kernel 5: IoU bitmask (skewed SoA smem, exact early-exit gating) --------
__global__ void __launch_bounds__(256) iou_kernel() {
    int b = blockIdx.y;
    int warp = threadIdx.x >> 5, lane = threadIdx.x & 31;
    int r = blockIdx.x * 8 + warp;
    __shared__ float sx1[1056], sy1[1056], sx2[1056], sy2[1056], sar[1056];
    for (int j = threadIdx.x; j < PRE; j += 256) {
        float4 v = ((const float4*)g_boxes)[b * PRE + j];
        int jj = j + (j >> 5);                 // skew: lane-stride-32 -> conflict-free
        sx1[jj] = v.x; sy1[jj] = v.y; sx2[jj] = v.z; sy2[jj] = v.w;
        float w0 = fmaxf(__fsub_rn(v.z, v.x), 0.0f);
        float h0 = fmaxf(__fsub_rn(v.w, v.y), 0.0f);
        sar[jj] = __fmul_rn(w0, h0);
    }
    __syncthreads();
    int rr = r + (r >> 5);
    float bx1 = sx1[rr], by1 = sy1[rr], bx2 = sx2[rr], by2 = sy2[rr], ar = sar[rr];
    unsigned word = 0u;
    int jbase = lane * 32;
    if (jbase + 31 > r) {
        int jjb = lane * 33;
#pragma unroll
        for (int k = 0; k < 32; k++) {
            int j = jbase + k;
            if (j > r) {
                // exact gate: if rx<=lx then reference iw==0 -> inter==0 -> iou==0
                // -> bit provably 0. Same for y. When gate passes, iw=rx-lx equals
                // fmaxf(rx-lx,0) exactly (operand positive) -> bit-identical result.
                float lx = fmaxf(bx1, sx1[jjb + k]);
                float rx = fminf(bx2, sx2[jjb + k]);
                if (rx > lx) {
                    float ly = fmaxf(by1, sy1[jjb + k]);
                    float ry = fminf(by2, sy2[jjb + k]);
                    if (ry > ly) {
                        float iw = __fsub_rn(rx, lx);
                        float ih = __fsub_rn(ry, ly);
                        float inter = __fmul_rn(iw, ih);
                        float aj = sar[jjb + k];
                        float denom = __fadd_rn(__fsub_rn(__fadd_rn(ar, aj), inter), 1e-7f);
                        if ((inter / denom) > IOU_T) word |= (1u << k);
                    }
                }
            }
        }
    }
    g_mask[((size_t)b * PRE + r) * 32 + lane] = word;
}

// ---------------- kernel 6: NMS scan over smem-staged masks + top-300 out -------
__global__ void __launch_bounds__(256) nms_kernel(float* __restrict__ out) {
    extern __shared__ unsigned sh[];
    unsigned* smask  = sh;                          // PRE*32 words (128 KB)
    float*    sscore = (float*)(sh + PRE * 32);     // PRE floats
    __shared__ unsigned svalid[32];
    __shared__ unsigned skeep[32];
    __shared__ unsigned kpre[33];
    int b = blockIdx.x, t = threadIdx.x;

    // stage masks (coalesced uint4) + scores/validity
    const uint4* gm4 = (const uint4*)(g_mask + (size_t)b * PRE * 32);
    uint4* sm4 = (uint4*)smask;
    for (int j = t; j < PRE * 8; j += 256) sm4[j] = gm4[j];
    for (int it = 0; it < 4; it++) {
        int e = it * 256 + t;
        float sc = g_selscore[b * PRE + e];
        sscore[e] = sc;
        unsigned bl = __ballot_sync(0xffffffffu, sc > 0.0f);
        if ((t & 31) == 0) svalid[it * 8 + (t >> 5)] = bl;
    }
    __syncthreads();

    // warp 0: word-parallel scan (lane = distributed suppression word)
    if (t < 32) {
        unsigned sup = 0u, mykeep = 0u;
        for (int w = 0; w < 32; w++) {
            unsigned m[32];
#pragma unroll
            for (int k = 0; k < 32; k++) m[k] = smask[(w * 32 + k) * 32 + t];
            unsigned kw = 0u;
            if (t == w) {
                unsigned ss = sup, vw = svalid[w];
#pragma unroll
                for (int k = 0; k < 32; k++) {
                    unsigned bit = 1u << k;
                    if ((vw & bit) && !(ss & bit)) { kw |= bit; ss |= m[k]; }
                }
                sup = ss;
            }
            kw = __shfl_sync(0xffffffffu, kw, w);
            if (t == w) {
                mykeep = kw;
            } else {
#pragma unroll
                for (int k = 0; k < 32; k++)
                    if (kw & (1u << k)) sup |= m[k];
            }
        }
        skeep[t] = mykeep;
    }
    __syncthreads();

    if (t < 32) {
        unsigned acc = 0;
        for (int q = 0; q < 32; q++) {
            if (q == t) kpre[t] = acc;
            acc += __popc(skeep[q]);
        }
        if (t == 31) kpre[32] = acc;
    }
    __syncthreads();
    unsigned total = kpre[32];

    for (int e = t; e < PRE; e += 256) {
        int w = e >> 5, bit = e & 31;
        int rank = kpre[w] + __popc(skeep[w] & ((1u << bit) - 1u));
        bool kp = (skeep[w] >> bit) & 1u;
        int orow = -1; float osc = 0.0f;
        if (kp) {
            if (rank < MAXD) { orow = rank; osc = sscore[e]; }
        } else {
            int nr = e - rank;
            if ((int)total + nr < MAXD) orow = (int)total + nr;
        }
        if (orow >= 0) {
            float4 bx = ((const float4*)g_boxes)[b * PRE + e];
            float cc = g_cls[b * PRE + e];
            float* o = out + ((size_t)b * MAXD + orow) * 6;
            o[0] = bx.x; o[1] = bx.y; o[2] = bx.z; o[3] = bx.w;
            o[4] = osc;  o[5] = cc;
        }
    }
}

// ---------------- launch ----------------
extern "C" void kernel_launch(void* const* d_in, const int* in_sizes, int n_in,
                              void* d_out, int out_size) {
    const float* pred = (const float*)d_in[0];
    float* out = (float*)d_out;

    const int nms_smem = (PRE * 32 + PRE) * 4;      // 135168 bytes
    cudaFuncSetAttribute(nms_kernel, cudaFuncAttributeMaxDynamicSharedMemorySize, nms_smem);

    score_kernel<<<dim3((NANCH + 255) / 256, BATCH), 256>>>(pred);
    thresh_kernel<<<BATCH, 1024>>>();
    gatherk_kernel<<<dim3((NANCH / 4 + 255) / 256, BATCH), 256>>>();
    sortg_kernel<<<BATCH, 1024>>>(pred);
    iou_kernel<<<dim3(PRE / 8, BATCH), 256>>>();
    nms_kernel<<<BATCH, 256, nms_smem>>>(out);
}